// round 13
// baseline (speedup 1.0000x reference)
#include <cuda_runtime.h>
#include <cuda_bf16.h>
#include <math.h>
#include <stdint.h>

// Problem constants
#define B_  4
#define S_  2048
#define H_  2048
#define NH_ 16
#define HD_ 128
#define MTOK (B_*S_)              // 8192 tokens
#define ELEMS (MTOK*H_)           // 16777216 per [B,S,H] buffer
#define SCALE_ 0.08838834764831845f  // 1/sqrt(128)

// -------- scratch (device globals; allocation-free per harness rules) --------
static __device__ float g_q   [ELEMS];
static __device__ float g_k   [ELEMS];
static __device__ float g_v   [ELEMS];
static __device__ float g_ctx [ELEMS];
static __device__ float g_attn[ELEMS];
static __device__ float g_ectx[ELEMS];
static __device__ float g_eout[ELEMS];

// bf16 hi/lo split buffers
static __device__ __nv_bfloat16 g_ah[ELEMS];
static __device__ __nv_bfloat16 g_al[ELEMS];
static __device__ __nv_bfloat16 g_wth[5][H_*H_];   // transposed weight hi
static __device__ __nv_bfloat16 g_wtl[5][H_*H_];   // transposed weight lo

// ============================================================================
// helpers
// ============================================================================
__device__ __forceinline__ uint32_t smem_u32(const void* p) {
    uint32_t a;
    asm("{ .reg .u64 t; cvta.to.shared.u64 t, %1; cvt.u32.u64 %0, t; }" : "=r"(a) : "l"(p));
    return a;
}
__device__ __forceinline__ uint32_t swz128(uint32_t off) {
    return off ^ ((off >> 3) & 0x70);
}
__device__ __forceinline__ void ldmx4(uint32_t* d, uint32_t addr) {
    asm volatile("ldmatrix.sync.aligned.m8n8.x4.shared.b16 {%0,%1,%2,%3}, [%4];"
                 : "=r"(d[0]), "=r"(d[1]), "=r"(d[2]), "=r"(d[3]) : "r"(addr));
}
__device__ __forceinline__ void mma_bf16(float* c, const uint32_t* a, const uint32_t* b) {
    asm volatile(
        "mma.sync.aligned.m16n8k16.row.col.f32.bf16.bf16.f32 "
        "{%0,%1,%2,%3}, {%4,%5,%6,%7}, {%8,%9}, {%0,%1,%2,%3};"
        : "+f"(c[0]), "+f"(c[1]), "+f"(c[2]), "+f"(c[3])
        : "r"(a[0]), "r"(a[1]), "r"(a[2]), "r"(a[3]), "r"(b[0]), "r"(b[1]));
}
__device__ __forceinline__ void cp_async16(uint32_t sa, const void* g) {
    asm volatile("cp.async.cg.shared.global [%0], [%1], 16;" :: "r"(sa), "l"(g));
}

// ============================================================================
// Kernel A: fp32 -> bf16 hi/lo split, elementwise
// ============================================================================
__global__ __launch_bounds__(256) void split_kernel(
    const float* __restrict__ in, __nv_bfloat16* __restrict__ hi,
    __nv_bfloat16* __restrict__ lo, int n4)
{
    const int i = blockIdx.x * 256 + threadIdx.x;
    if (i >= n4) return;
    const float4 v = ((const float4*)in)[i];
    __nv_bfloat16 h[4], l[4];
    const float vv[4] = {v.x, v.y, v.z, v.w};
#pragma unroll
    for (int j = 0; j < 4; j++) {
        h[j] = __float2bfloat16(vv[j]);
        l[j] = __float2bfloat16(vv[j] - __bfloat162float(h[j]));
    }
    *(uint2*)(hi + 4 * (size_t)i) = *(const uint2*)&h[0];
    *(uint2*)(lo + 4 * (size_t)i) = *(const uint2*)&l[0];
}

// ============================================================================
// Kernel B: W [K,N] fp32 -> Wt [N,K] bf16 hi/lo (transpose + split)
// ============================================================================
__global__ __launch_bounds__(256) void transpose_split(
    const float* __restrict__ W, __nv_bfloat16* __restrict__ Th,
    __nv_bfloat16* __restrict__ Tl)
{
    __shared__ float t[32][33];
    const int n0 = blockIdx.x * 32, k0 = blockIdx.y * 32;
    const int x = threadIdx.x, y = threadIdx.y;   // 32 x 8
#pragma unroll
    for (int i = 0; i < 32; i += 8)
        t[y + i][x] = W[(size_t)(k0 + y + i) * H_ + n0 + x];
    __syncthreads();
#pragma unroll
    for (int i = 0; i < 32; i += 8) {
        const float v = t[x][y + i];   // W[k0+x][n0+y+i]
        const __nv_bfloat16 h = __float2bfloat16(v);
        const size_t o = (size_t)(n0 + y + i) * H_ + k0 + x;
        Th[o] = h;
        Tl[o] = __float2bfloat16(v - __bfloat162float(h));
    }
}

// ============================================================================
// Kernel C: mma.sync bf16-split GEMM.  C[M,N] = (Ah+Al) @ (Bh+Bl)^T
// A: [M,K] bf16 row-major; B: [N,K] bf16 row-major (pre-transposed weights).
// CTA 128x128, BK=64, cp.async 2-stage double buffer, 8 warps (2x4),
// warp tile 64x32, m16n8k16, 3 passes (hh, hl, lh).
// ============================================================================
#define TILE_B  16384                 // one 128x64 bf16 tile (128B rows)
#define STAGE_B (4 * TILE_B)          // Ah,Al,Bh,Bl
#define GEMM_SMEM (2 * STAGE_B)       // 131072

__global__ __launch_bounds__(256) void gemm_mma_split(
    const __nv_bfloat16* __restrict__ Ah, const __nv_bfloat16* __restrict__ Al,
    const __nv_bfloat16* __restrict__ Bh, const __nv_bfloat16* __restrict__ Bl,
    float* __restrict__ C, int M, int N, int K)
{
    extern __shared__ __align__(128) char smem[];
    const uint32_t sb = smem_u32(smem);
    const int tid    = threadIdx.x;
    const int lane   = tid & 31;
    const int wid    = tid >> 5;
    const int warp_m = wid >> 2;          // 0..1 -> rows warp_m*64
    const int warp_n = wid & 3;           // 0..3 -> cols warp_n*32
    const int bm = blockIdx.y * 128;
    const int bn = blockIdx.x * 128;

    const __nv_bfloat16* srcs[4] = {Ah, Al, Bh, Bl};
    const int nchunk = K >> 6;            // K/64

    // ---- async prefetch of one K-chunk into stage buf ----
    auto prefetch = [&](int kc, int buf) {
        const int k0 = kc * 64;
        const uint32_t base = sb + buf * STAGE_B;
#pragma unroll
        for (int t4 = 0; t4 < 4; t4++) {
            const __nv_bfloat16* src =
                srcs[t4] + (size_t)((t4 >= 2) ? bn : bm) * K + k0;
            const uint32_t tb = base + t4 * TILE_B;
#pragma unroll
            for (int i = 0; i < 4; i++) {
                const int idx = i * 256 + tid;         // 1024 segs: 128 rows x 8
                const int r = idx >> 3, s = idx & 7;
                cp_async16(tb + swz128((uint32_t)(r * 128 + s * 16)),
                           src + (size_t)r * K + s * 8);
            }
        }
        asm volatile("cp.async.commit_group;" ::: "memory");
    };

    float acc[4][4][4];
#pragma unroll
    for (int mt = 0; mt < 4; mt++)
#pragma unroll
        for (int nt = 0; nt < 4; nt++)
#pragma unroll
            for (int j = 0; j < 4; j++) acc[mt][nt][j] = 0.0f;

    // per-thread ldmatrix address components
    const int a_r  = warp_m * 64 + (lane & 7) + (((lane >> 3) & 1) << 3);
    const int a_kb = ((lane >> 4) & 1) << 4;
    const int b_r  = warp_n * 32 + (lane & 7) + (((lane >> 4) & 1) << 3);
    const int b_kb = ((lane >> 3) & 1) << 4;

    prefetch(0, 0);

    for (int kc = 0; kc < nchunk; kc++) {
        const int buf = kc & 1;
        if (kc + 1 < nchunk) {
            prefetch(kc + 1, buf ^ 1);
            asm volatile("cp.async.wait_group 1;" ::: "memory");
        } else {
            asm volatile("cp.async.wait_group 0;" ::: "memory");
        }
        __syncthreads();

        const uint32_t ah_b = sb + buf * STAGE_B;
        const uint32_t al_b = ah_b + TILE_B;
        const uint32_t bh_b = ah_b + 2 * TILE_B;
        const uint32_t bl_b = ah_b + 3 * TILE_B;

#pragma unroll
        for (int ks = 0; ks < 4; ks++) {
            const int kbyte = ks * 32;
            uint32_t fah[4][4], fal[4][4], fbh[4][2], fbl[4][2];
#pragma unroll
            for (int mt = 0; mt < 4; mt++) {
                const uint32_t off =
                    swz128((uint32_t)((a_r + mt * 16) * 128 + kbyte + a_kb));
                ldmx4(fah[mt], ah_b + off);
                ldmx4(fal[mt], al_b + off);
            }
#pragma unroll
            for (int bt = 0; bt < 2; bt++) {
                const uint32_t off =
                    swz128((uint32_t)((b_r + bt * 16) * 128 + kbyte + b_kb));
                uint32_t d[4];
                ldmx4(d, bh_b + off);
                fbh[2 * bt][0] = d[0]; fbh[2 * bt][1] = d[1];
                fbh[2 * bt + 1][0] = d[2]; fbh[2 * bt + 1][1] = d[3];
                ldmx4(d, bl_b + off);
                fbl[2 * bt][0] = d[0]; fbl[2 * bt][1] = d[1];
                fbl[2 * bt + 1][0] = d[2]; fbl[2 * bt + 1][1] = d[3];
            }
#pragma unroll
            for (int mt = 0; mt < 4; mt++)
#pragma unroll
                for (int nt = 0; nt < 4; nt++) {
                    mma_bf16(acc[mt][nt], fah[mt], fbh[nt]);   // hi*hi
                    mma_bf16(acc[mt][nt], fah[mt], fbl[nt]);   // hi*lo
                    mma_bf16(acc[mt][nt], fal[mt], fbh[nt]);   // lo*hi
                }
        }
        __syncthreads();
    }

    // epilogue: c0,c1 at (m=t/4, n=2(t%4)); c2,c3 at (m+8, n)
    const int em = bm + warp_m * 64 + (lane >> 2);
    const int en = bn + warp_n * 32 + 2 * (lane & 3);
#pragma unroll
    for (int mt = 0; mt < 4; mt++)
#pragma unroll
        for (int nt = 0; nt < 4; nt++) {
            float* p0 = C + (size_t)(em + mt * 16) * N + en + nt * 8;
            float* p1 = p0 + 8 * (size_t)N;
            *(float2*)p0 = make_float2(acc[mt][nt][0], acc[mt][nt][1]);
            *(float2*)p1 = make_float2(acc[mt][nt][2], acc[mt][nt][3]);
        }
}

// ============================================================================
// Kernel 2: causal flash attention fp32
// ============================================================================
#define QS_STR 65
#define PS_STR 68
#define PM_STR 17
#define OFF_QS   0
#define OFF_KS   (OFF_QS + 128 * QS_STR)
#define OFF_VS   (OFF_KS + 128 * QS_STR)
#define OFF_PS   (OFF_VS + 64 * 128)
#define OFF_PMAX (OFF_PS + 64 * PS_STR)
#define OFF_PSUM (OFF_PMAX + 64 * PM_STR)
#define OFF_M    (OFF_PSUM + 64 * PM_STR)
#define OFF_L    (OFF_M + 64)
#define OFF_FAC  (OFF_L + 64)
#define FLASH_SMEM_FLOATS (OFF_FAC + 64)
#define FLASH_SMEM_BYTES  (FLASH_SMEM_FLOATS * 4)

__global__ __launch_bounds__(256) void flash_attn(
    const float* __restrict__ Q, const float* __restrict__ Kmat,
    const float* __restrict__ Vmat, float* __restrict__ O)
{
    extern __shared__ float sm[];
    float* Qs   = sm + OFF_QS;
    float* Ks   = sm + OFF_KS;
    float* Vs   = sm + OFF_VS;
    float* Ps   = sm + OFF_PS;
    float* pmax = sm + OFF_PMAX;
    float* psum = sm + OFF_PSUM;
    float* m_s  = sm + OFF_M;
    float* l_s  = sm + OFF_L;
    float* fac  = sm + OFF_FAC;

    const int tid  = threadIdx.x;
    const int tx   = tid & 15;
    const int ty   = tid >> 4;
    const int q0   = blockIdx.x * 64;
    const int head = blockIdx.y;
    const int b    = blockIdx.z;

    const size_t rowbase = (size_t)b * S_ * H_ + (size_t)head * HD_;

    for (int idx = tid; idx < 64 * 32; idx += 256) {
        const int qi = idx >> 5;
        const int d4 = (idx & 31) * 4;
        float4 v = *(const float4*)(Q + rowbase + (size_t)(q0 + qi) * H_ + d4);
        Qs[(d4 + 0) * QS_STR + qi] = v.x;
        Qs[(d4 + 1) * QS_STR + qi] = v.y;
        Qs[(d4 + 2) * QS_STR + qi] = v.z;
        Qs[(d4 + 3) * QS_STR + qi] = v.w;
    }
    if (tid < 64) { m_s[tid] = -1e30f; l_s[tid] = 0.0f; }

    float acc[4][8];
#pragma unroll
    for (int i = 0; i < 4; i++)
#pragma unroll
        for (int j = 0; j < 8; j++) acc[i][j] = 0.0f;

    const int ntiles = (q0 >> 6) + 1;
    __syncthreads();

    for (int kt = 0; kt < ntiles; kt++) {
        const int k0 = kt * 64;
        for (int idx = tid; idx < 64 * 32; idx += 256) {
            const int ki = idx >> 5;
            const int d4 = (idx & 31) * 4;
            const float4 kv = *(const float4*)(Kmat + rowbase + (size_t)(k0 + ki) * H_ + d4);
            Ks[(d4 + 0) * QS_STR + ki] = kv.x;
            Ks[(d4 + 1) * QS_STR + ki] = kv.y;
            Ks[(d4 + 2) * QS_STR + ki] = kv.z;
            Ks[(d4 + 3) * QS_STR + ki] = kv.w;
            *(float4*)&Vs[ki * 128 + d4] =
                *(const float4*)(Vmat + rowbase + (size_t)(k0 + ki) * H_ + d4);
        }
        __syncthreads();

        float s[4][4];
#pragma unroll
        for (int i = 0; i < 4; i++)
#pragma unroll
            for (int j = 0; j < 4; j++) s[i][j] = 0.0f;

#pragma unroll 8
        for (int d = 0; d < 128; d++) {
            float rq[4], rk[4];
#pragma unroll
            for (int i = 0; i < 4; i++) rq[i] = Qs[d * QS_STR + ty * 4 + i];
#pragma unroll
            for (int j = 0; j < 4; j++) rk[j] = Ks[d * QS_STR + tx * 4 + j];
#pragma unroll
            for (int i = 0; i < 4; i++)
#pragma unroll
                for (int j = 0; j < 4; j++)
                    s[i][j] += rq[i] * rk[j];
        }
#pragma unroll
        for (int i = 0; i < 4; i++) {
            const int qg = q0 + ty * 4 + i;
            float rmax = -1e30f;
#pragma unroll
            for (int j = 0; j < 4; j++) {
                const int kg = k0 + tx * 4 + j;
                float val = (kg <= qg) ? s[i][j] * SCALE_ : -1e30f;
                s[i][j] = val;
                rmax = fmaxf(rmax, val);
            }
            pmax[(ty * 4 + i) * PM_STR + tx] = rmax;
        }
        __syncthreads();

        if (tid < 64) {
            float tm = -1e30f;
#pragma unroll
            for (int t = 0; t < 16; t++) tm = fmaxf(tm, pmax[tid * PM_STR + t]);
            const float m_old = m_s[tid];
            const float m_new = fmaxf(m_old, tm);
            const float f = expf(m_old - m_new);
            m_s[tid] = m_new;
            fac[tid] = f;
            l_s[tid] *= f;
        }
        __syncthreads();

#pragma unroll
        for (int i = 0; i < 4; i++) {
            const float mi = m_s[ty * 4 + i];
            float p0 = expf(s[i][0] - mi);
            float p1 = expf(s[i][1] - mi);
            float p2 = expf(s[i][2] - mi);
            float p3 = expf(s[i][3] - mi);
            *(float4*)&Ps[(ty * 4 + i) * PS_STR + tx * 4] = make_float4(p0, p1, p2, p3);
            psum[(ty * 4 + i) * PM_STR + tx] = p0 + p1 + p2 + p3;
        }
        __syncthreads();

        if (tid < 64) {
            float add = 0.0f;
#pragma unroll
            for (int t = 0; t < 16; t++) add += psum[tid * PM_STR + t];
            l_s[tid] += add;
        }

        float fi[4];
#pragma unroll
        for (int i = 0; i < 4; i++) fi[i] = fac[ty * 4 + i];
#pragma unroll
        for (int i = 0; i < 4; i++)
#pragma unroll
            for (int j = 0; j < 8; j++) acc[i][j] *= fi[i];

#pragma unroll 4
        for (int kk = 0; kk < 64; kk++) {
            float rp[4];
#pragma unroll
            for (int i = 0; i < 4; i++) rp[i] = Ps[(ty * 4 + i) * PS_STR + kk];
            const float4 v0 = *(const float4*)&Vs[kk * 128 + tx * 8];
            const float4 v1 = *(const float4*)&Vs[kk * 128 + tx * 8 + 4];
#pragma unroll
            for (int i = 0; i < 4; i++) {
                acc[i][0] += rp[i] * v0.x;
                acc[i][1] += rp[i] * v0.y;
                acc[i][2] += rp[i] * v0.z;
                acc[i][3] += rp[i] * v0.w;
                acc[i][4] += rp[i] * v1.x;
                acc[i][5] += rp[i] * v1.y;
                acc[i][6] += rp[i] * v1.z;
                acc[i][7] += rp[i] * v1.w;
            }
        }
        __syncthreads();
    }

#pragma unroll
    for (int i = 0; i < 4; i++) {
        const float inv = 1.0f / l_s[ty * 4 + i];
        float* orow = O + rowbase + (size_t)(q0 + ty * 4 + i) * H_ + tx * 8;
        *(float4*)orow =
            make_float4(acc[i][0] * inv, acc[i][1] * inv, acc[i][2] * inv, acc[i][3] * inv);
        *(float4*)(orow + 4) =
            make_float4(acc[i][4] * inv, acc[i][5] * inv, acc[i][6] * inv, acc[i][7] * inv);
    }
}

// ============================================================================
// Kernel 3: external memory attention (HBM-bound)
// ============================================================================
__global__ __launch_bounds__(256) void ext_attn(
    const float* __restrict__ A, const float* __restrict__ EK,
    const float* __restrict__ EV, float* __restrict__ O)
{
    const int gw   = blockIdx.x * 8 + (threadIdx.x >> 5);
    const int lane = threadIdx.x & 31;
    const int b = gw >> 15;
    const int rem = gw & 32767;
    const int h = rem >> 11;
    const int s = rem & 2047;

    const size_t abase = ((size_t)(b * S_ + s)) * H_ + h * HD_ + lane * 4;
    const float4 q = *(const float4*)(A + abase);
    const size_t ebase = (size_t)gw * 1024 + lane * 4;

    float sc[8];
#pragma unroll
    for (int kk = 0; kk < 8; kk++) {
        const float4 kv = *(const float4*)(EK + ebase + kk * 128);
        float p = q.x * kv.x + q.y * kv.y + q.z * kv.z + q.w * kv.w;
        p += __shfl_xor_sync(0xffffffffu, p, 16);
        p += __shfl_xor_sync(0xffffffffu, p, 8);
        p += __shfl_xor_sync(0xffffffffu, p, 4);
        p += __shfl_xor_sync(0xffffffffu, p, 2);
        p += __shfl_xor_sync(0xffffffffu, p, 1);
        sc[kk] = p * SCALE_;
    }
    float m = sc[0];
#pragma unroll
    for (int kk = 1; kk < 8; kk++) m = fmaxf(m, sc[kk]);
    float w[8], sum = 0.0f;
#pragma unroll
    for (int kk = 0; kk < 8; kk++) { w[kk] = expf(sc[kk] - m); sum += w[kk]; }
    const float inv = 1.0f / sum;

    float4 acc = make_float4(0.f, 0.f, 0.f, 0.f);
#pragma unroll
    for (int kk = 0; kk < 8; kk++) {
        const float4 vv = *(const float4*)(EV + ebase + kk * 128);
        acc.x += w[kk] * vv.x;
        acc.y += w[kk] * vv.y;
        acc.z += w[kk] * vv.z;
        acc.w += w[kk] * vv.w;
    }
    acc.x *= inv; acc.y *= inv; acc.z *= inv; acc.w *= inv;
    *(float4*)(O + abase) = acc;
}

// ============================================================================
// Kernel 4: gate + combine
// ============================================================================
__global__ __launch_bounds__(256) void gate_combine(
    const float* __restrict__ X, const float* __restrict__ Wg,
    const float* __restrict__ bg, const float* __restrict__ attn,
    const float* __restrict__ ext, float* __restrict__ out)
{
    const int t = blockIdx.x;
    const int tid = threadIdx.x;
    __shared__ float r0[256], r1[256];
    __shared__ float g0s, g1s;

    const float* x = X + (size_t)t * H_;
    float p0 = 0.0f, p1 = 0.0f;
    for (int h = tid; h < H_; h += 256) {
        const float xv = x[h];
        p0 += xv * Wg[h * 3 + 0];
        p1 += xv * Wg[h * 3 + 1];
    }
    r0[tid] = p0; r1[tid] = p1;
    __syncthreads();
    for (int sft = 128; sft > 0; sft >>= 1) {
        if (tid < sft) { r0[tid] += r0[tid + sft]; r1[tid] += r1[tid + sft]; }
        __syncthreads();
    }
    if (tid == 0) {
        const float l0 = r0[0] + bg[0];
        const float l1 = r1[0] + bg[1];
        const float m = fmaxf(l0, l1);
        const float e0 = expf(l0 - m), e1 = expf(l1 - m);
        const float inv = 1.0f / (e0 + e1);
        g0s = e0 * inv; g1s = e1 * inv;
    }
    __syncthreads();
    const float g0 = g0s, g1 = g1s;
    const size_t base4 = (size_t)t * (H_ / 4);
    const float4* a4 = (const float4*)attn + base4;
    const float4* e4 = (const float4*)ext + base4;
    float4* o4 = (float4*)out + base4;
    for (int h4 = tid; h4 < H_ / 4; h4 += 256) {
        const float4 a = a4[h4];
        const float4 e = e4[h4];
        o4[h4] = make_float4(g0 * a.x + g1 * e.x, g0 * a.y + g1 * e.y,
                             g0 * a.z + g1 * e.z, g0 * a.w + g1 * e.w);
    }
}

// ============================================================================
// Launch
// ============================================================================
extern "C" void kernel_launch(void* const* d_in, const int* in_sizes, int n_in,
                              void* d_out, int out_size)
{
    const float* X    = (const float*)d_in[0];
    const float* ek   = (const float*)d_in[1];
    const float* ev   = (const float*)d_in[2];
    const float* W[5] = {(const float*)d_in[3], (const float*)d_in[4],
                         (const float*)d_in[5], (const float*)d_in[6],
                         (const float*)d_in[7]};                       // Wq,Wk,Wv,Wo,Wext
    const float* Wg   = (const float*)d_in[8];
    const float* bg   = (const float*)d_in[9];
    float* out = (float*)d_out;

    float *qb, *kb, *vb, *ctxb, *attnb, *ectxb, *eoutb;
    cudaGetSymbolAddress((void**)&qb,    g_q);
    cudaGetSymbolAddress((void**)&kb,    g_k);
    cudaGetSymbolAddress((void**)&vb,    g_v);
    cudaGetSymbolAddress((void**)&ctxb,  g_ctx);
    cudaGetSymbolAddress((void**)&attnb, g_attn);
    cudaGetSymbolAddress((void**)&ectxb, g_ectx);
    cudaGetSymbolAddress((void**)&eoutb, g_eout);

    __nv_bfloat16 *ah, *al, *wth, *wtl;
    cudaGetSymbolAddress((void**)&ah,  g_ah);
    cudaGetSymbolAddress((void**)&al,  g_al);
    cudaGetSymbolAddress((void**)&wth, g_wth);
    cudaGetSymbolAddress((void**)&wtl, g_wtl);

    cudaFuncSetAttribute(gemm_mma_split, cudaFuncAttributeMaxDynamicSharedMemorySize, GEMM_SMEM);
    cudaFuncSetAttribute(flash_attn, cudaFuncAttributeMaxDynamicSharedMemorySize, FLASH_SMEM_BYTES);

    const int n4 = ELEMS / 4;
    const dim3 tg(H_ / 32, H_ / 32), tb(32, 8);
    const dim3 gg(H_ / 128, MTOK / 128);   // (16, 64)

    // weight transposes + splits
    for (int i = 0; i < 5; i++)
        transpose_split<<<tg, tb>>>(W[i], wth + (size_t)i * H_ * H_, wtl + (size_t)i * H_ * H_);

    // X split + QKV projections (tensor core)
    split_kernel<<<(n4 + 255) / 256, 256>>>(X, ah, al, n4);
    gemm_mma_split<<<gg, 256, GEMM_SMEM>>>(ah, al, wth + 0 * (size_t)H_ * H_, wtl + 0 * (size_t)H_ * H_, qb, MTOK, H_, H_);
    gemm_mma_split<<<gg, 256, GEMM_SMEM>>>(ah, al, wth + 1 * (size_t)H_ * H_, wtl + 1 * (size_t)H_ * H_, kb, MTOK, H_, H_);
    gemm_mma_split<<<gg, 256, GEMM_SMEM>>>(ah, al, wth + 2 * (size_t)H_ * H_, wtl + 2 * (size_t)H_ * H_, vb, MTOK, H_, H_);

    // causal flash attention
    flash_attn<<<dim3(S_ / 64, NH_, B_), 256, FLASH_SMEM_BYTES>>>(qb, kb, vb, ctxb);

    // output projection
    split_kernel<<<(n4 + 255) / 256, 256>>>(ctxb, ah, al, n4);
    gemm_mma_split<<<gg, 256, GEMM_SMEM>>>(ah, al, wth + 3 * (size_t)H_ * H_, wtl + 3 * (size_t)H_ * H_, attnb, MTOK, H_, H_);

    // external memory attention
    ext_attn<<<(B_ * NH_ * S_) / 8, 256>>>(attnb, ek, ev, ectxb);

    // external projection
    split_kernel<<<(n4 + 255) / 256, 256>>>(ectxb, ah, al, n4);
    gemm_mma_split<<<gg, 256, GEMM_SMEM>>>(ah, al, wth + 4 * (size_t)H_ * H_, wtl + 4 * (size_t)H_ * H_, eoutb, MTOK, H_, H_);

    // gate + combine
    gate_combine<<<MTOK, 256>>>(X, Wg, bg, attnb, eoutb, out);
}

// round 14
// speedup vs baseline: 1.6568x; 1.6568x over previous
#include <cuda_runtime.h>
#include <cuda_bf16.h>
#include <math.h>
#include <stdint.h>

// Problem constants
#define B_  4
#define S_  2048
#define H_  2048
#define NH_ 16
#define HD_ 128
#define MTOK (B_*S_)              // 8192 tokens
#define ELEMS (MTOK*H_)           // 16777216
#define SCALE_ 0.08838834764831845f  // 1/sqrt(128)

// -------- scratch (device globals; allocation-free) --------
static __device__ float g_attn[ELEMS];
static __device__ float g_eout[ELEMS];
static __device__ __nv_bfloat16 g_ah[ELEMS], g_al[ELEMS];   // generic split buf (X / ctx / ectx)
static __device__ __nv_bfloat16 g_qh[ELEMS], g_ql[ELEMS];
static __device__ __nv_bfloat16 g_kh[ELEMS], g_kl[ELEMS];
static __device__ __nv_bfloat16 g_vh[ELEMS], g_vl[ELEMS];
static __device__ __nv_bfloat16 g_wth[5][H_*H_], g_wtl[5][H_*H_];

// ============================================================================
// helpers
// ============================================================================
__device__ __forceinline__ uint32_t smem_u32(const void* p) {
    uint32_t a;
    asm("{ .reg .u64 t; cvta.to.shared.u64 t, %1; cvt.u32.u64 %0, t; }" : "=r"(a) : "l"(p));
    return a;
}
__device__ __forceinline__ uint32_t swz128(uint32_t off) {
    return off ^ ((off >> 3) & 0x70);
}
__device__ __forceinline__ void ldmx4(uint32_t* d, uint32_t addr) {
    asm volatile("ldmatrix.sync.aligned.m8n8.x4.shared.b16 {%0,%1,%2,%3}, [%4];"
                 : "=r"(d[0]), "=r"(d[1]), "=r"(d[2]), "=r"(d[3]) : "r"(addr));
}
__device__ __forceinline__ void ldmx4t(uint32_t* d, uint32_t addr) {
    asm volatile("ldmatrix.sync.aligned.m8n8.x4.trans.shared.b16 {%0,%1,%2,%3}, [%4];"
                 : "=r"(d[0]), "=r"(d[1]), "=r"(d[2]), "=r"(d[3]) : "r"(addr));
}
__device__ __forceinline__ void mma_bf16(float* c, const uint32_t* a, const uint32_t* b) {
    asm volatile(
        "mma.sync.aligned.m16n8k16.row.col.f32.bf16.bf16.f32 "
        "{%0,%1,%2,%3}, {%4,%5,%6,%7}, {%8,%9}, {%0,%1,%2,%3};"
        : "+f"(c[0]), "+f"(c[1]), "+f"(c[2]), "+f"(c[3])
        : "r"(a[0]), "r"(a[1]), "r"(a[2]), "r"(a[3]), "r"(b[0]), "r"(b[1]));
}
__device__ __forceinline__ void cp_async16(uint32_t sa, const void* g) {
    asm volatile("cp.async.cg.shared.global [%0], [%1], 16;" :: "r"(sa), "l"(g));
}
__device__ __forceinline__ uint32_t pack2bf(float x, float y) {
    __nv_bfloat162 t = __floats2bfloat162_rn(x, y);
    return *reinterpret_cast<uint32_t*>(&t);
}

// ============================================================================
// Kernel A: fp32 -> bf16 hi/lo split, elementwise
// ============================================================================
__global__ __launch_bounds__(256) void split_kernel(
    const float* __restrict__ in, __nv_bfloat16* __restrict__ hi,
    __nv_bfloat16* __restrict__ lo, int n4)
{
    const int i = blockIdx.x * 256 + threadIdx.x;
    if (i >= n4) return;
    const float4 v = ((const float4*)in)[i];
    __nv_bfloat16 h[4], l[4];
    const float vv[4] = {v.x, v.y, v.z, v.w};
#pragma unroll
    for (int j = 0; j < 4; j++) {
        h[j] = __float2bfloat16(vv[j]);
        l[j] = __float2bfloat16(vv[j] - __bfloat162float(h[j]));
    }
    *(uint2*)(hi + 4 * (size_t)i) = *(const uint2*)&h[0];
    *(uint2*)(lo + 4 * (size_t)i) = *(const uint2*)&l[0];
}

// ============================================================================
// Kernel B: W [K,N] fp32 -> Wt [N,K] bf16 hi/lo
// ============================================================================
__global__ __launch_bounds__(256) void transpose_split(
    const float* __restrict__ W, __nv_bfloat16* __restrict__ Th,
    __nv_bfloat16* __restrict__ Tl)
{
    __shared__ float t[32][33];
    const int n0 = blockIdx.x * 32, k0 = blockIdx.y * 32;
    const int x = threadIdx.x, y = threadIdx.y;
#pragma unroll
    for (int i = 0; i < 32; i += 8)
        t[y + i][x] = W[(size_t)(k0 + y + i) * H_ + n0 + x];
    __syncthreads();
#pragma unroll
    for (int i = 0; i < 32; i += 8) {
        const float v = t[x][y + i];
        const __nv_bfloat16 h = __float2bfloat16(v);
        const size_t o = (size_t)(n0 + y + i) * H_ + k0 + x;
        Th[o] = h;
        Tl[o] = __float2bfloat16(v - __bfloat162float(h));
    }
}

// ============================================================================
// Kernel C: mma.sync bf16-split GEMM.  C = (Ah+Al) @ (Bh+Bl)^T
// OUTMODE 0: fp32 C.  OUTMODE 1: bf16 hi/lo split output, scaled by oscale.
// ============================================================================
#define TILE_B  16384
#define STAGE_B (4 * TILE_B)
#define GEMM_SMEM (2 * STAGE_B)       // 131072

template<int OUTMODE>
__global__ __launch_bounds__(256) void gemm_mma_split(
    const __nv_bfloat16* __restrict__ Ah, const __nv_bfloat16* __restrict__ Al,
    const __nv_bfloat16* __restrict__ Bh, const __nv_bfloat16* __restrict__ Bl,
    float* __restrict__ C, __nv_bfloat16* __restrict__ Ch,
    __nv_bfloat16* __restrict__ Cl, float oscale, int M, int N, int K)
{
    extern __shared__ __align__(128) char smem[];
    const uint32_t sb = smem_u32(smem);
    const int tid    = threadIdx.x;
    const int lane   = tid & 31;
    const int wid    = tid >> 5;
    const int warp_m = wid >> 2;
    const int warp_n = wid & 3;
    const int bm = blockIdx.y * 128;
    const int bn = blockIdx.x * 128;

    const __nv_bfloat16* srcs[4] = {Ah, Al, Bh, Bl};
    const int nchunk = K >> 6;

    auto prefetch = [&](int kc, int buf) {
        const int k0 = kc * 64;
        const uint32_t base = sb + buf * STAGE_B;
#pragma unroll
        for (int t4 = 0; t4 < 4; t4++) {
            const __nv_bfloat16* src =
                srcs[t4] + (size_t)((t4 >= 2) ? bn : bm) * K + k0;
            const uint32_t tb = base + t4 * TILE_B;
#pragma unroll
            for (int i = 0; i < 4; i++) {
                const int idx = i * 256 + tid;
                const int r = idx >> 3, s = idx & 7;
                cp_async16(tb + swz128((uint32_t)(r * 128 + s * 16)),
                           src + (size_t)r * K + s * 8);
            }
        }
        asm volatile("cp.async.commit_group;" ::: "memory");
    };

    float acc[4][4][4];
#pragma unroll
    for (int mt = 0; mt < 4; mt++)
#pragma unroll
        for (int nt = 0; nt < 4; nt++)
#pragma unroll
            for (int j = 0; j < 4; j++) acc[mt][nt][j] = 0.0f;

    const int a_r  = warp_m * 64 + (lane & 7) + (((lane >> 3) & 1) << 3);
    const int a_kb = ((lane >> 4) & 1) << 4;
    const int b_r  = warp_n * 32 + (lane & 7) + (((lane >> 4) & 1) << 3);
    const int b_kb = ((lane >> 3) & 1) << 4;

    prefetch(0, 0);

    for (int kc = 0; kc < nchunk; kc++) {
        const int buf = kc & 1;
        if (kc + 1 < nchunk) {
            prefetch(kc + 1, buf ^ 1);
            asm volatile("cp.async.wait_group 1;" ::: "memory");
        } else {
            asm volatile("cp.async.wait_group 0;" ::: "memory");
        }
        __syncthreads();

        const uint32_t ah_b = sb + buf * STAGE_B;
        const uint32_t al_b = ah_b + TILE_B;
        const uint32_t bh_b = ah_b + 2 * TILE_B;
        const uint32_t bl_b = ah_b + 3 * TILE_B;

#pragma unroll
        for (int ks = 0; ks < 4; ks++) {
            const int kbyte = ks * 32;
            uint32_t fah[4][4], fal[4][4], fbh[4][2], fbl[4][2];
#pragma unroll
            for (int mt = 0; mt < 4; mt++) {
                const uint32_t off =
                    swz128((uint32_t)((a_r + mt * 16) * 128 + kbyte + a_kb));
                ldmx4(fah[mt], ah_b + off);
                ldmx4(fal[mt], al_b + off);
            }
#pragma unroll
            for (int bt = 0; bt < 2; bt++) {
                const uint32_t off =
                    swz128((uint32_t)((b_r + bt * 16) * 128 + kbyte + b_kb));
                uint32_t d[4];
                ldmx4(d, bh_b + off);
                fbh[2 * bt][0] = d[0]; fbh[2 * bt][1] = d[1];
                fbh[2 * bt + 1][0] = d[2]; fbh[2 * bt + 1][1] = d[3];
                ldmx4(d, bl_b + off);
                fbl[2 * bt][0] = d[0]; fbl[2 * bt][1] = d[1];
                fbl[2 * bt + 1][0] = d[2]; fbl[2 * bt + 1][1] = d[3];
            }
#pragma unroll
            for (int mt = 0; mt < 4; mt++)
#pragma unroll
                for (int nt = 0; nt < 4; nt++) {
                    mma_bf16(acc[mt][nt], fah[mt], fbh[nt]);
                    mma_bf16(acc[mt][nt], fah[mt], fbl[nt]);
                    mma_bf16(acc[mt][nt], fal[mt], fbh[nt]);
                }
        }
        __syncthreads();
    }

    const int em = bm + warp_m * 64 + (lane >> 2);
    const int en = bn + warp_n * 32 + 2 * (lane & 3);
#pragma unroll
    for (int mt = 0; mt < 4; mt++)
#pragma unroll
        for (int nt = 0; nt < 4; nt++) {
            if (OUTMODE == 0) {
                float* p0 = C + (size_t)(em + mt * 16) * N + en + nt * 8;
                float* p1 = p0 + 8 * (size_t)N;
                *(float2*)p0 = make_float2(acc[mt][nt][0], acc[mt][nt][1]);
                *(float2*)p1 = make_float2(acc[mt][nt][2], acc[mt][nt][3]);
            } else {
                const float v0 = acc[mt][nt][0] * oscale;
                const float v1 = acc[mt][nt][1] * oscale;
                const float v2 = acc[mt][nt][2] * oscale;
                const float v3 = acc[mt][nt][3] * oscale;
                const __nv_bfloat16 h0 = __float2bfloat16(v0), h1 = __float2bfloat16(v1);
                const __nv_bfloat16 h2 = __float2bfloat16(v2), h3 = __float2bfloat16(v3);
                const size_t o0 = (size_t)(em + mt * 16) * N + en + nt * 8;
                const size_t o1 = o0 + 8 * (size_t)N;
                *(uint32_t*)(Ch + o0) = pack2bf(__bfloat162float(h0), __bfloat162float(h1));
                *(uint32_t*)(Ch + o1) = pack2bf(__bfloat162float(h2), __bfloat162float(h3));
                *(uint32_t*)(Cl + o0) = pack2bf(v0 - __bfloat162float(h0), v1 - __bfloat162float(h1));
                *(uint32_t*)(Cl + o1) = pack2bf(v2 - __bfloat162float(h2), v3 - __bfloat162float(h3));
            }
        }
}

// ============================================================================
// Kernel 2: tensor-core causal flash attention, bf16 hi/lo split precision.
// BQ=128 (CTA), BK=64, 8 warps each own 16 q-rows fully. Outputs ctx hi/lo.
// ============================================================================
#define FL_STR   272                    // padded smem row stride (bytes)
#define FL_KT    (64 * FL_STR)          // 17408, one 64-row K/V subtile
#define FL_STAGE (4 * FL_KT)            // 69632: KH,KL,VH,VL
#define FL_SMEM  (2 * FL_STAGE)         // 139264

__global__ __launch_bounds__(256) void flash_tc(
    const __nv_bfloat16* __restrict__ Qh, const __nv_bfloat16* __restrict__ Ql,
    const __nv_bfloat16* __restrict__ Kh, const __nv_bfloat16* __restrict__ Kl,
    const __nv_bfloat16* __restrict__ Vh, const __nv_bfloat16* __restrict__ Vl,
    __nv_bfloat16* __restrict__ Ch, __nv_bfloat16* __restrict__ Cl)
{
    extern __shared__ __align__(128) char smem[];
    const uint32_t sb = smem_u32(smem);
    const int tid = threadIdx.x, lane = tid & 31, wid = tid >> 5;
    const int qt   = (int)(gridDim.x - 1 - blockIdx.x);   // heavy tiles first
    const int q0   = qt * 128;
    const int head = blockIdx.y, b = blockIdx.z;
    const size_t tokbase = (size_t)b * S_ * H_ + (size_t)head * HD_;

    // ---- load Q tile (hi+lo) into smem, then to register fragments ----
    {
        const __nv_bfloat16* qs[2] = {Qh, Ql};
#pragma unroll
        for (int i = 0; i < 16; i++) {
            const int idx = i * 256 + tid;           // 4096 = 2 tiles x 128 rows x 16
            const int t = idx >> 11, r = (idx >> 4) & 127, c = idx & 15;
            cp_async16(sb + (uint32_t)(t * 34816 + r * FL_STR + c * 16),
                       qs[t] + tokbase + (size_t)(q0 + r) * H_ + c * 8);
        }
        asm volatile("cp.async.commit_group;" ::: "memory");
        asm volatile("cp.async.wait_group 0;" ::: "memory");
        __syncthreads();
    }
    uint32_t aqh[8][4], aql[8][4];
    {
        const int arow = wid * 16 + (lane & 15);
        const int acb  = (lane >> 4) * 16;
#pragma unroll
        for (int s = 0; s < 8; s++) {
            ldmx4(aqh[s], sb + (uint32_t)(arow * FL_STR + s * 32 + acb));
            ldmx4(aql[s], sb + (uint32_t)(34816 + arow * FL_STR + s * 32 + acb));
        }
    }
    __syncthreads();   // smem now free for K/V stages

    const __nv_bfloat16* kvsrc[4] = {Kh, Kl, Vh, Vl};
    auto prefetch = [&](int kt, int buf) {
        const int k0 = kt * 64;
#pragma unroll
        for (int t4 = 0; t4 < 4; t4++) {
            const __nv_bfloat16* src = kvsrc[t4] + tokbase;
            const uint32_t db = sb + (uint32_t)(buf * FL_STAGE + t4 * FL_KT);
#pragma unroll
            for (int i = 0; i < 4; i++) {
                const int idx = i * 256 + tid;
                const int r = idx >> 4, c = idx & 15;
                cp_async16(db + (uint32_t)(r * FL_STR + c * 16),
                           src + (size_t)(k0 + r) * H_ + c * 8);
            }
        }
        asm volatile("cp.async.commit_group;" ::: "memory");
    };

    float oacc[16][4];
#pragma unroll
    for (int nt = 0; nt < 16; nt++)
#pragma unroll
        for (int j = 0; j < 4; j++) oacc[nt][j] = 0.0f;
    float m0 = -1e30f, m1 = -1e30f, l0 = 0.0f, l1 = 0.0f;

    const int nkt = 2 * qt + 2;
    const int qw0 = q0 + wid * 16;

    prefetch(0, 0);

    for (int kt = 0; kt < nkt; kt++) {
        const int buf = kt & 1;
        const int k0  = kt * 64;
        if (kt + 1 < nkt) {
            prefetch(kt + 1, buf ^ 1);
            asm volatile("cp.async.wait_group 1;" ::: "memory");
        } else {
            asm volatile("cp.async.wait_group 0;" ::: "memory");
        }
        __syncthreads();

        if (k0 <= qw0 + 15) {   // warp not fully masked
            const uint32_t khb = sb + (uint32_t)(buf * FL_STAGE);
            const uint32_t klb = khb + FL_KT;
            const uint32_t vhb = khb + 2 * FL_KT;
            const uint32_t vlb = khb + 3 * FL_KT;

            // ---- scores S[16 x 64] per warp, 3-pass split ----
            float sacc[8][4];
#pragma unroll
            for (int nt = 0; nt < 8; nt++)
#pragma unroll
                for (int j = 0; j < 4; j++) sacc[nt][j] = 0.0f;

            const int krow = (lane & 7) + ((lane >> 4) << 3);
            const int kcb  = ((lane >> 3) & 1) << 4;
#pragma unroll
            for (int s = 0; s < 8; s++) {
                uint32_t kf[4][4], lf[4][4];
#pragma unroll
                for (int p = 0; p < 4; p++) {
                    const uint32_t off = (uint32_t)((16 * p + krow) * FL_STR + s * 32 + kcb);
                    ldmx4(kf[p], khb + off);
                    ldmx4(lf[p], klb + off);
                }
#pragma unroll
                for (int p = 0; p < 4; p++) {
                    mma_bf16(sacc[2 * p],     aqh[s], &kf[p][0]);
                    mma_bf16(sacc[2 * p + 1], aqh[s], &kf[p][2]);
                    mma_bf16(sacc[2 * p],     aqh[s], &lf[p][0]);
                    mma_bf16(sacc[2 * p + 1], aqh[s], &lf[p][2]);
                    mma_bf16(sacc[2 * p],     aql[s], &kf[p][0]);
                    mma_bf16(sacc[2 * p + 1], aql[s], &kf[p][2]);
                }
            }

            // ---- causal mask (boundary tiles only) ----
            if (k0 + 63 > qw0) {
                const int qg = qw0 + (lane >> 2);
                const int kg = k0 + 2 * (lane & 3);
#pragma unroll
                for (int nt = 0; nt < 8; nt++)
#pragma unroll
                    for (int j = 0; j < 4; j++)
                        if (kg + 8 * nt + (j & 1) > qg + 8 * (j >> 1))
                            sacc[nt][j] = -1e30f;
            }

            // ---- online softmax (warp-local rows) ----
            float r0 = -1e30f, r1 = -1e30f;
#pragma unroll
            for (int nt = 0; nt < 8; nt++) {
                r0 = fmaxf(r0, fmaxf(sacc[nt][0], sacc[nt][1]));
                r1 = fmaxf(r1, fmaxf(sacc[nt][2], sacc[nt][3]));
            }
            r0 = fmaxf(r0, __shfl_xor_sync(0xffffffffu, r0, 1));
            r0 = fmaxf(r0, __shfl_xor_sync(0xffffffffu, r0, 2));
            r1 = fmaxf(r1, __shfl_xor_sync(0xffffffffu, r1, 1));
            r1 = fmaxf(r1, __shfl_xor_sync(0xffffffffu, r1, 2));
            const float mn0 = fmaxf(m0, r0), mn1 = fmaxf(m1, r1);
            const float f0 = __expf(m0 - mn0), f1 = __expf(m1 - mn1);
            m0 = mn0; m1 = mn1;

            float rs0 = 0.0f, rs1 = 0.0f;
            uint32_t pah[4][4], pal[4][4];
#pragma unroll
            for (int nt = 0; nt < 8; nt++) {
                const float p0 = __expf(sacc[nt][0] - m0);
                const float p1 = __expf(sacc[nt][1] - m0);
                const float p2 = __expf(sacc[nt][2] - m1);
                const float p3 = __expf(sacc[nt][3] - m1);
                rs0 += p0 + p1; rs1 += p2 + p3;
                const __nv_bfloat16 h0 = __float2bfloat16(p0), h1 = __float2bfloat16(p1);
                const __nv_bfloat16 h2 = __float2bfloat16(p2), h3 = __float2bfloat16(p3);
                const int s2 = nt >> 1, o = (nt & 1) * 2;
                pah[s2][o]     = pack2bf(__bfloat162float(h0), __bfloat162float(h1));
                pah[s2][o + 1] = pack2bf(__bfloat162float(h2), __bfloat162float(h3));
                pal[s2][o]     = pack2bf(p0 - __bfloat162float(h0), p1 - __bfloat162float(h1));
                pal[s2][o + 1] = pack2bf(p2 - __bfloat162float(h2), p3 - __bfloat162float(h3));
            }
            rs0 += __shfl_xor_sync(0xffffffffu, rs0, 1);
            rs0 += __shfl_xor_sync(0xffffffffu, rs0, 2);
            rs1 += __shfl_xor_sync(0xffffffffu, rs1, 1);
            rs1 += __shfl_xor_sync(0xffffffffu, rs1, 2);
            l0 = l0 * f0 + rs0;
            l1 = l1 * f1 + rs1;
#pragma unroll
            for (int nt = 0; nt < 16; nt++) {
                oacc[nt][0] *= f0; oacc[nt][1] *= f0;
                oacc[nt][2] *= f1; oacc[nt][3] *= f1;
            }

            // ---- PV: O[16 x 128] += P[16 x 64] @ V[64 x 128], 3-pass split ----
            const int vrow = lane & 15;
            const int vcb  = (lane >> 4) << 4;
#pragma unroll
            for (int s2 = 0; s2 < 4; s2++) {
#pragma unroll
                for (int half = 0; half < 2; half++) {
                    uint32_t vf[4][4], wf[4][4];
#pragma unroll
                    for (int p = 0; p < 4; p++) {
                        const uint32_t off =
                            (uint32_t)((16 * s2 + vrow) * FL_STR + (half * 4 + p) * 32 + vcb);
                        ldmx4t(vf[p], vhb + off);
                        ldmx4t(wf[p], vlb + off);
                    }
#pragma unroll
                    for (int p = 0; p < 4; p++) {
                        const int nt = half * 8 + 2 * p;
                        mma_bf16(oacc[nt],     pah[s2], &vf[p][0]);
                        mma_bf16(oacc[nt + 1], pah[s2], &vf[p][2]);
                        mma_bf16(oacc[nt],     pah[s2], &wf[p][0]);
                        mma_bf16(oacc[nt + 1], pah[s2], &wf[p][2]);
                        mma_bf16(oacc[nt],     pal[s2], &vf[p][0]);
                        mma_bf16(oacc[nt + 1], pal[s2], &vf[p][2]);
                    }
                }
            }
        }
        __syncthreads();
    }

    // ---- epilogue: normalize, split to bf16 hi/lo, write ctx ----
    const float il0 = 1.0f / l0, il1 = 1.0f / l1;
    const int gr0 = q0 + wid * 16 + (lane >> 2);
#pragma unroll
    for (int nt = 0; nt < 16; nt++) {
        const int col = nt * 8 + 2 * (lane & 3);
        const float v0 = oacc[nt][0] * il0, v1 = oacc[nt][1] * il0;
        const float v2 = oacc[nt][2] * il1, v3 = oacc[nt][3] * il1;
        const __nv_bfloat16 h0 = __float2bfloat16(v0), h1 = __float2bfloat16(v1);
        const __nv_bfloat16 h2 = __float2bfloat16(v2), h3 = __float2bfloat16(v3);
        const size_t o0 = tokbase + (size_t)gr0 * H_ + col;
        const size_t o1 = o0 + 8 * (size_t)H_;
        *(uint32_t*)(Ch + o0) = pack2bf(__bfloat162float(h0), __bfloat162float(h1));
        *(uint32_t*)(Ch + o1) = pack2bf(__bfloat162float(h2), __bfloat162float(h3));
        *(uint32_t*)(Cl + o0) = pack2bf(v0 - __bfloat162float(h0), v1 - __bfloat162float(h1));
        *(uint32_t*)(Cl + o1) = pack2bf(v2 - __bfloat162float(h2), v3 - __bfloat162float(h3));
    }
}

// ============================================================================
// Kernel 3: external memory attention (HBM-bound), split bf16 output
// ============================================================================
__global__ __launch_bounds__(256) void ext_attn(
    const float* __restrict__ A, const float* __restrict__ EK,
    const float* __restrict__ EV, __nv_bfloat16* __restrict__ Oh,
    __nv_bfloat16* __restrict__ Ol)
{
    const int gw   = blockIdx.x * 8 + (threadIdx.x >> 5);
    const int lane = threadIdx.x & 31;
    const int b = gw >> 15;
    const int rem = gw & 32767;
    const int h = rem >> 11;
    const int s = rem & 2047;

    const size_t abase = ((size_t)(b * S_ + s)) * H_ + h * HD_ + lane * 4;
    const float4 q = *(const float4*)(A + abase);
    const size_t ebase = (size_t)gw * 1024 + lane * 4;

    float sc[8];
#pragma unroll
    for (int kk = 0; kk < 8; kk++) {
        const float4 kv = *(const float4*)(EK + ebase + kk * 128);
        float p = q.x * kv.x + q.y * kv.y + q.z * kv.z + q.w * kv.w;
        p += __shfl_xor_sync(0xffffffffu, p, 16);
        p += __shfl_xor_sync(0xffffffffu, p, 8);
        p += __shfl_xor_sync(0xffffffffu, p, 4);
        p += __shfl_xor_sync(0xffffffffu, p, 2);
        p += __shfl_xor_sync(0xffffffffu, p, 1);
        sc[kk] = p * SCALE_;
    }
    float m = sc[0];
#pragma unroll
    for (int kk = 1; kk < 8; kk++) m = fmaxf(m, sc[kk]);
    float w[8], sum = 0.0f;
#pragma unroll
    for (int kk = 0; kk < 8; kk++) { w[kk] = __expf(sc[kk] - m); sum += w[kk]; }
    const float inv = 1.0f / sum;

    float acc[4] = {0.f, 0.f, 0.f, 0.f};
#pragma unroll
    for (int kk = 0; kk < 8; kk++) {
        const float4 vv = *(const float4*)(EV + ebase + kk * 128);
        acc[0] += w[kk] * vv.x;
        acc[1] += w[kk] * vv.y;
        acc[2] += w[kk] * vv.z;
        acc[3] += w[kk] * vv.w;
    }
    __nv_bfloat16 hh[4], ll[4];
#pragma unroll
    for (int j = 0; j < 4; j++) {
        const float v = acc[j] * inv;
        hh[j] = __float2bfloat16(v);
        ll[j] = __float2bfloat16(v - __bfloat162float(hh[j]));
    }
    *(uint2*)(Oh + abase) = *(const uint2*)&hh[0];
    *(uint2*)(Ol + abase) = *(const uint2*)&ll[0];
}

// ============================================================================
// Kernel 4: gate + combine
// ============================================================================
__global__ __launch_bounds__(256) void gate_combine(
    const float* __restrict__ X, const float* __restrict__ Wg,
    const float* __restrict__ bg, const float* __restrict__ attn,
    const float* __restrict__ ext, float* __restrict__ out)
{
    const int t = blockIdx.x;
    const int tid = threadIdx.x;
    __shared__ float r0[256], r1[256];
    __shared__ float g0s, g1s;

    const float* x = X + (size_t)t * H_;
    float p0 = 0.0f, p1 = 0.0f;
    for (int h = tid; h < H_; h += 256) {
        const float xv = x[h];
        p0 += xv * Wg[h * 3 + 0];
        p1 += xv * Wg[h * 3 + 1];
    }
    r0[tid] = p0; r1[tid] = p1;
    __syncthreads();
    for (int sft = 128; sft > 0; sft >>= 1) {
        if (tid < sft) { r0[tid] += r0[tid + sft]; r1[tid] += r1[tid + sft]; }
        __syncthreads();
    }
    if (tid == 0) {
        const float l0 = r0[0] + bg[0];
        const float l1 = r1[0] + bg[1];
        const float m = fmaxf(l0, l1);
        const float e0 = expf(l0 - m), e1 = expf(l1 - m);
        const float inv = 1.0f / (e0 + e1);
        g0s = e0 * inv; g1s = e1 * inv;
    }
    __syncthreads();
    const float g0 = g0s, g1 = g1s;
    const size_t base4 = (size_t)t * (H_ / 4);
    const float4* a4 = (const float4*)attn + base4;
    const float4* e4 = (const float4*)ext + base4;
    float4* o4 = (float4*)out + base4;
    for (int h4 = tid; h4 < H_ / 4; h4 += 256) {
        const float4 a = a4[h4];
        const float4 e = e4[h4];
        o4[h4] = make_float4(g0 * a.x + g1 * e.x, g0 * a.y + g1 * e.y,
                             g0 * a.z + g1 * e.z, g0 * a.w + g1 * e.w);
    }
}

// ============================================================================
// Launch
// ============================================================================
extern "C" void kernel_launch(void* const* d_in, const int* in_sizes, int n_in,
                              void* d_out, int out_size)
{
    const float* X    = (const float*)d_in[0];
    const float* ek   = (const float*)d_in[1];
    const float* ev   = (const float*)d_in[2];
    const float* W[5] = {(const float*)d_in[3], (const float*)d_in[4],
                         (const float*)d_in[5], (const float*)d_in[6],
                         (const float*)d_in[7]};
    const float* Wg   = (const float*)d_in[8];
    const float* bg   = (const float*)d_in[9];
    float* out = (float*)d_out;

    float *attnb, *eoutb;
    cudaGetSymbolAddress((void**)&attnb, g_attn);
    cudaGetSymbolAddress((void**)&eoutb, g_eout);

    __nv_bfloat16 *ah, *al, *qh, *ql, *kh, *kl, *vh, *vl, *wth, *wtl;
    cudaGetSymbolAddress((void**)&ah, g_ah);
    cudaGetSymbolAddress((void**)&al, g_al);
    cudaGetSymbolAddress((void**)&qh, g_qh);
    cudaGetSymbolAddress((void**)&ql, g_ql);
    cudaGetSymbolAddress((void**)&kh, g_kh);
    cudaGetSymbolAddress((void**)&kl, g_kl);
    cudaGetSymbolAddress((void**)&vh, g_vh);
    cudaGetSymbolAddress((void**)&vl, g_vl);
    cudaGetSymbolAddress((void**)&wth, g_wth);
    cudaGetSymbolAddress((void**)&wtl, g_wtl);

    cudaFuncSetAttribute(gemm_mma_split<0>, cudaFuncAttributeMaxDynamicSharedMemorySize, GEMM_SMEM);
    cudaFuncSetAttribute(gemm_mma_split<1>, cudaFuncAttributeMaxDynamicSharedMemorySize, GEMM_SMEM);
    cudaFuncSetAttribute(flash_tc, cudaFuncAttributeMaxDynamicSharedMemorySize, FL_SMEM);

    const int n4 = ELEMS / 4;
    const dim3 tg(H_ / 32, H_ / 32), tb(32, 8);
    const dim3 gg(H_ / 128, MTOK / 128);   // (16, 64)

    // weight transposes + splits
    for (int i = 0; i < 5; i++)
        transpose_split<<<tg, tb>>>(W[i], wth + (size_t)i * H_ * H_, wtl + (size_t)i * H_ * H_);

    // X split + QKV projections (split bf16 outputs; scale folded into Q)
    split_kernel<<<(n4 + 255) / 256, 256>>>(X, ah, al, n4);
    gemm_mma_split<1><<<gg, 256, GEMM_SMEM>>>(ah, al, wth + 0 * (size_t)H_ * H_, wtl + 0 * (size_t)H_ * H_,
                                              nullptr, qh, ql, SCALE_, MTOK, H_, H_);
    gemm_mma_split<1><<<gg, 256, GEMM_SMEM>>>(ah, al, wth + 1 * (size_t)H_ * H_, wtl + 1 * (size_t)H_ * H_,
                                              nullptr, kh, kl, 1.0f, MTOK, H_, H_);
    gemm_mma_split<1><<<gg, 256, GEMM_SMEM>>>(ah, al, wth + 2 * (size_t)H_ * H_, wtl + 2 * (size_t)H_ * H_,
                                              nullptr, vh, vl, 1.0f, MTOK, H_, H_);

    // tensor-core causal flash attention -> ctx split (reuses g_ah/g_al)
    flash_tc<<<dim3(S_ / 128, NH_, B_), 256, FL_SMEM>>>(qh, ql, kh, kl, vh, vl, ah, al);

    // output projection (fp32 out, needed by ext_attn + gate)
    gemm_mma_split<0><<<gg, 256, GEMM_SMEM>>>(ah, al, wth + 3 * (size_t)H_ * H_, wtl + 3 * (size_t)H_ * H_,
                                              attnb, nullptr, nullptr, 1.0f, MTOK, H_, H_);

    // external memory attention -> ectx split (reuses g_ah/g_al)
    ext_attn<<<(B_ * NH_ * S_) / 8, 256>>>(attnb, ek, ev, ah, al);

    // external projection
    gemm_mma_split<0><<<gg, 256, GEMM_SMEM>>>(ah, al, wth + 4 * (size_t)H_ * H_, wtl + 4 * (size_t)H_ * H_,
                                              eoutb, nullptr, nullptr, 1.0f, MTOK, H_, H_);

    // gate + combine
    gate_combine<<<MTOK, 256>>>(X, Wg, bg, attnb, eoutb, out);
}